// round 12
// baseline (speedup 1.0000x reference)
#include <cuda_runtime.h>
#include <cstdint>

#define NNODES 16384
#define NFEAT  300
#define NHID   512
#define NOUT   256
#define NACT   64
#define NEIGH  2048
#define SS     2112      // NACT + NEIGH
#define MAXNNZ 64

#define GEMM_BLOCKS 264                       // 33 row-tiles x 8 col-tiles of 64 (producers)
#define MAIN_BLOCKS (GEMM_BLOCKS + SS)        // 2376

// ---- scratch (static device globals; zero-initialized at module load) ----
__device__ int   g_loE[NNODES];    // atomicMax of (SS - j); 0 = absent; lo = SS - val
__device__ int   g_hiE[NNODES];    // atomicMax of (j + 1);  0 = absent; hi = val - 1
__device__ int   g_nnz[SS];
__device__ int   g_cols[SS * MAXNNZ];
__device__ float g_XW1[SS * NHID]; // x[cur] @ W1
__device__ float g_w[NHID];        // W2 @ imp_w
__device__ float g_u[SS];          // relu(A @ XW1) @ w
__device__ int   g_ready;          // producer arrivals (GEMM+gw), reset each replay
__device__ int   g_cons;           // consumer completions, reset each replay

__device__ __forceinline__ float warp_sum(float v) {
    #pragma unroll
    for (int o = 16; o > 0; o >>= 1) v += __shfl_xor_sync(0xFFFFFFFFu, v, o);
    return v;
}

__device__ __forceinline__ uint32_t f2tf(float x) {
    uint32_t r;
    asm("cvt.rna.tf32.f32 %0, %1;" : "=r"(r) : "f"(x));
    return r;
}

__device__ __forceinline__ void mma_tf32(float* d, const uint32_t* a, const uint32_t* b) {
    asm volatile(
        "mma.sync.aligned.m16n8k8.row.col.f32.tf32.tf32.f32 "
        "{%0,%1,%2,%3},{%4,%5,%6,%7},{%8,%9},{%0,%1,%2,%3};"
        : "+f"(d[0]), "+f"(d[1]), "+f"(d[2]), "+f"(d[3])
        : "r"(a[0]), "r"(a[1]), "r"(a[2]), "r"(a[3]), "r"(b[0]), "r"(b[1]));
}

// scatter-only prep: inverse map (idempotent atomicMax on zero-init arrays).
__global__ void k_scatter(const int* __restrict__ act, const int* __restrict__ nb) {
    int t = blockIdx.x * blockDim.x + threadIdx.x;
    if (t < SS) {
        int v = (t < NACT) ? act[t] : nb[t - NACT];
        atomicMax(&g_loE[v], SS - t);
        atomicMax(&g_hiE[v], t + 1);
    }
}

// ---------------------------------------------------------------------------
// fused main kernel (producer/consumer in one grid):
//   bid <  264 : producer — tf32 MMA GEMM tile; bid<128 also computes 4 g_w rows;
//                then threadfence + g_ready arrival.
//   bid >= 264 : extract row i = bid-264 (no XW1 needed), then wait g_ready==264,
//                then compute g_u[i] from the smem column list (layer2 fused).
// Producers are the lowest block indices -> all resident in wave 1 -> consumer
// spin cannot deadlock (work distributor schedules ascending bids).
// ---------------------------------------------------------------------------
#define AS_STRIDE 36
#define BS_STRIDE 72
#define SMEM_BYTES (64 * AS_STRIDE * 4 + 32 * BS_STRIDE * 4)

__global__ void __launch_bounds__(256, 4) k_main(const float* __restrict__ X,
                                                 const float* __restrict__ W1,
                                                 const float* __restrict__ adj,
                                                 const int* __restrict__ act,
                                                 const int* __restrict__ nb,
                                                 const float* __restrict__ W2,
                                                 const float* __restrict__ iw) {
    __shared__ __align__(16) char smem_raw[SMEM_BYTES];
    __shared__ float s_gw[8];
    int bid = blockIdx.x;
    int tid = threadIdx.x;

    if (bid < GEMM_BLOCKS) {
        // ================= producer: tf32 MMA GEMM tile =================
        int gidx = bid;
        int bm = (gidx >> 3) * 64;
        int bn = (gidx & 7) * 64;
        uint32_t* As = (uint32_t*)smem_raw;
        uint32_t* Bs = As + 64 * AS_STRIDE;
        int warp = tid >> 5, lane = tid & 31;
        int wr = warp >> 2;
        int wc = warp & 3;

        float acc[2][2][4] = {};

        for (int k0 = 0; k0 < NFEAT; k0 += 32) {
            #pragma unroll
            for (int r = 0; r < 2; r++) {
                int f = tid + r * 256;
                int m = f >> 3, c4 = f & 7;
                int k = k0 + c4 * 4;
                float4 v = make_float4(0.f, 0.f, 0.f, 0.f);
                if (k < NFEAT) {
                    int gr = bm + m;
                    int node = (gr < NACT) ? act[gr] : nb[gr - NACT];
                    v = *(const float4*)(X + (size_t)node * NFEAT + k);
                }
                uint4 u = make_uint4(f2tf(v.x), f2tf(v.y), f2tf(v.z), f2tf(v.w));
                *(uint4*)&As[m * AS_STRIDE + c4 * 4] = u;
            }
            #pragma unroll
            for (int r = 0; r < 2; r++) {
                int f = tid + r * 256;
                int kr = f >> 4, c4 = f & 15;
                int k = k0 + kr;
                float4 v = make_float4(0.f, 0.f, 0.f, 0.f);
                if (k < NFEAT) v = *(const float4*)(W1 + (size_t)k * NHID + bn + c4 * 4);
                uint4 u = make_uint4(f2tf(v.x), f2tf(v.y), f2tf(v.z), f2tf(v.w));
                *(uint4*)&Bs[kr * BS_STRIDE + c4 * 4] = u;
            }
            __syncthreads();
            #pragma unroll
            for (int kk = 0; kk < 32; kk += 8) {
                uint32_t a[2][4], b[2][2];
                #pragma unroll
                for (int ti = 0; ti < 2; ti++) {
                    int r0 = wr * 32 + ti * 16 + (lane >> 2);
                    int kc = kk + (lane & 3);
                    a[ti][0] = As[r0 * AS_STRIDE + kc];
                    a[ti][1] = As[(r0 + 8) * AS_STRIDE + kc];
                    a[ti][2] = As[r0 * AS_STRIDE + kc + 4];
                    a[ti][3] = As[(r0 + 8) * AS_STRIDE + kc + 4];
                }
                #pragma unroll
                for (int tj = 0; tj < 2; tj++) {
                    int col = wc * 16 + tj * 8 + (lane >> 2);
                    int kc = kk + (lane & 3);
                    b[tj][0] = Bs[kc * BS_STRIDE + col];
                    b[tj][1] = Bs[(kc + 4) * BS_STRIDE + col];
                }
                #pragma unroll
                for (int ti = 0; ti < 2; ti++)
                    #pragma unroll
                    for (int tj = 0; tj < 2; tj++)
                        mma_tf32(acc[ti][tj], a[ti], b[tj]);
            }
            __syncthreads();
        }
        int lane4 = (tid & 31) >> 2, lm = (tid & 3) * 2;
        #pragma unroll
        for (int ti = 0; ti < 2; ti++) {
            int row0 = bm + wr * 32 + ti * 16 + lane4;
            #pragma unroll
            for (int tj = 0; tj < 2; tj++) {
                int col0 = bn + wc * 16 + tj * 8 + lm;
                float* c = acc[ti][tj];
                *(float2*)&g_XW1[(size_t)row0 * NHID + col0]       = make_float2(c[0], c[1]);
                *(float2*)&g_XW1[(size_t)(row0 + 8) * NHID + col0] = make_float2(c[2], c[3]);
            }
        }

        // first 128 producers also compute g_w (4 rows each, 64 threads/row)
        if (bid < 128) {
            int row = bid * 4 + (tid >> 6);
            int t64 = tid & 63;
            float4 wv = *(const float4*)(W2 + (size_t)row * NOUT + t64 * 4);
            float4 iv = *(const float4*)(iw + t64 * 4);
            float p = wv.x * iv.x + wv.y * iv.y + wv.z * iv.z + wv.w * iv.w;
            p = warp_sum(p);
            if (lane == 0) s_gw[warp] = p;
            __syncthreads();
            if (t64 == 0) g_w[row] = s_gw[(tid >> 6) * 2] + s_gw[(tid >> 6) * 2 + 1];
        }

        __threadfence();
        if (tid == 0) atomicAdd(&g_ready, 1);
    } else {
        // ========== consumer: extract row, then fused layer2 for that row ==========
        int i = bid - GEMM_BLOCKS;          // 0..2111
        int* s_cols   = (int*)smem_raw;
        int* s_sorted = s_cols + MAXNNZ;
        int* s_cntp   = s_sorted + MAXNNZ;
        float* s_red  = (float*)(s_cntp + 4);
        if (tid == 0) *s_cntp = 0;
        __syncthreads();
        int node = (i < NACT) ? act[i] : nb[i - NACT];
        const float4* row = (const float4*)(adj + (size_t)node * NNODES);
        #pragma unroll 4
        for (int it = 0; it < NNODES / 4 / 256; it++) {
            int p = it * 256 + tid;
            float4 v = __ldcs(row + p);
            if (v.x != 0.f || v.y != 0.f || v.z != 0.f || v.w != 0.f) {
                float e[4] = {v.x, v.y, v.z, v.w};
                #pragma unroll
                for (int q = 0; q < 4; q++) {
                    if (e[q] != 0.f) {
                        int col = p * 4 + q;
                        int lov = g_loE[col];
                        if (lov > 0) {
                            int lo = SS - lov;
                            int k = atomicAdd(s_cntp, 1);
                            if (k < MAXNNZ) s_cols[k] = lo;
                            int hi = g_hiE[col] - 1;
                            if (hi != lo) {
                                k = atomicAdd(s_cntp, 1);
                                if (k < MAXNNZ) s_cols[k] = hi;
                            }
                        }
                    }
                }
            }
        }
        __syncthreads();
        int n = min(*s_cntp, MAXNNZ);
        if (tid < n) {                      // rank-sort (values distinct)
            int val = s_cols[tid];
            int rank = 0;
            for (int k = 0; k < n; k++) rank += (s_cols[k] < val);
            s_sorted[rank] = val;
        }
        __syncthreads();
        if (tid == 0) g_nnz[i] = n;
        if (tid < n) g_cols[i * MAXNNZ + tid] = s_sorted[tid];

        // wait for producers (GEMM + g_w); in practice already done
        if (tid == 0) {
            while (atomicAdd(&g_ready, 0) < GEMM_BLOCKS) { }
        }
        __syncthreads();
        __threadfence();

        // fused layer2 for row i: u = relu(sum_k XW1[c_k]) . w
        float a0 = 0.f, a1 = 0.f;
        for (int k0 = 0; k0 < n; k0 += 4) {
            float v0[4], v1[4];
            #pragma unroll
            for (int q = 0; q < 4; q++) {
                float x0 = 0.f, x1 = 0.f;
                if (k0 + q < n) {
                    const float* s = g_XW1 + (size_t)s_sorted[k0 + q] * NHID;
                    x0 = s[tid];
                    x1 = s[tid + 256];
                }
                v0[q] = x0; v1[q] = x1;
            }
            #pragma unroll
            for (int q = 0; q < 4; q++) { a0 += v0[q]; a1 += v1[q]; }
        }
        float p = fmaxf(a0, 0.f) * g_w[tid] + fmaxf(a1, 0.f) * g_w[tid + 256];
        p = warp_sum(p);
        if ((tid & 31) == 0) s_red[tid >> 5] = p;
        __syncthreads();
        if (tid == 0) {
            float s = 0.f;
            #pragma unroll
            for (int w = 0; w < 8; w++) s += s_red[w];
            g_u[i] = s;
            __threadfence();
            // consumer completion; last consumer resets counters for next replay
            if (atomicAdd(&g_cons, 1) == SS - 1) {
                g_ready = 0;
                g_cons = 0;
            }
        }
    }
}

// finalize (known-good, 1024 threads): v = A@u; imp = A@v + b; L1-normalize.
__global__ void k_finalize(const float* __restrict__ impb, const int* __restrict__ nb,
                           float* __restrict__ out, int out_size) {
    __shared__ float s_u[SS];
    __shared__ float s_v[SS];
    __shared__ float s_imp[SS];
    __shared__ float s_red[32];
    __shared__ float s_tot;
    int tid = threadIdx.x;

    for (int j = tid; j < SS; j += 1024) s_u[j] = g_u[j];
    __syncthreads();

    for (int i = tid; i < SS; i += 1024) {
        int nnz = g_nnz[i];
        const int4* cp4 = (const int4*)(g_cols + i * MAXNNZ);
        float a = 0.f;
        for (int k0 = 0; k0 < nnz; k0 += 4) {
            int4 c = cp4[k0 >> 2];
            if (k0 + 0 < nnz) a += s_u[c.x];
            if (k0 + 1 < nnz) a += s_u[c.y];
            if (k0 + 2 < nnz) a += s_u[c.z];
            if (k0 + 3 < nnz) a += s_u[c.w];
        }
        s_v[i] = a;
    }
    __syncthreads();

    float b = impb[0];
    float part = 0.f;
    for (int i = tid; i < SS; i += 1024) {
        int nnz = g_nnz[i];
        const int4* cp4 = (const int4*)(g_cols + i * MAXNNZ);
        float a = b;
        for (int k0 = 0; k0 < nnz; k0 += 4) {
            int4 c = cp4[k0 >> 2];
            if (k0 + 0 < nnz) a += s_v[c.x];
            if (k0 + 1 < nnz) a += s_v[c.y];
            if (k0 + 2 < nnz) a += s_v[c.z];
            if (k0 + 3 < nnz) a += s_v[c.w];
        }
        s_imp[i] = a;
        part += fabsf(a);
    }
    part = warp_sum(part);
    if ((tid & 31) == 0) s_red[tid >> 5] = part;
    __syncthreads();
    if (tid == 0) {
        float s = 0.f;
        #pragma unroll
        for (int w = 0; w < 32; w++) s += s_red[w];
        s_tot = s;
    }
    __syncthreads();
    float inv = 1.f / fmaxf(s_tot, 1e-12f);
    for (int j = tid; j < NEIGH; j += 1024) out[j] = s_imp[NACT + j] * inv;
    if (out_size >= 2 * NEIGH)
        for (int j = tid; j < NEIGH; j += 1024) out[NEIGH + j] = (float)nb[j];
}

extern "C" void kernel_launch(void* const* d_in, const int* in_sizes, int n_in,
                              void* d_out, int out_size) {
    const float* x   = (const float*)d_in[0];
    const float* adj = (const float*)d_in[1];
    const int*   act = (const int*)d_in[2];
    const int*   nb  = (const int*)d_in[3];
    const float* W1  = (const float*)d_in[4];
    const float* W2  = (const float*)d_in[5];
    const float* iw  = (const float*)d_in[6];
    const float* ib  = (const float*)d_in[7];
    float* out = (float*)d_out;
    (void)in_sizes; (void)n_in;

    k_scatter<<<(SS + 255) / 256, 256>>>(act, nb);
    k_main<<<MAIN_BLOCKS, 256>>>(x, W1, adj, act, nb, W2, iw);
    k_finalize<<<1, 1024>>>(ib, nb, out, out_size);
}

// round 15
// speedup vs baseline: 1.1086x; 1.1086x over previous
#include <cuda_runtime.h>
#include <cstdint>

#define NNODES 16384
#define NFEAT  300
#define NHID   512
#define NOUT   256
#define NACT   64
#define NEIGH  2048
#define SS     2112      // NACT + NEIGH
#define MAXNNZ 64

#define GEMM_BLOCKS 264                       // 33 row-tiles x 8 col-tiles of 64
#define EXTRACT_END (GEMM_BLOCKS + SS)        // 2376 = 264 * 9
#define W_BLOCKS    128                       // g_w reduction: 4 rows/block
#define MAIN_BLOCKS (EXTRACT_END + W_BLOCKS)  // 2504

// ---- scratch (static device globals; zero-initialized at module load) ----
__device__ int   g_loE[NNODES];    // atomicMax of (SS - j); 0 = absent; lo = SS - val
__device__ int   g_hiE[NNODES];    // atomicMax of (j + 1);  0 = absent; hi = val - 1
__device__ int   g_nnz[SS];
__device__ int   g_cols[SS * MAXNNZ];
__device__ float g_XW1[SS * NHID]; // x[cur] @ W1
__device__ float g_w[NHID];        // W2 @ imp_w
__device__ float g_u[SS];          // relu(A @ XW1) @ w

__device__ __forceinline__ float warp_sum(float v) {
    #pragma unroll
    for (int o = 16; o > 0; o >>= 1) v += __shfl_xor_sync(0xFFFFFFFFu, v, o);
    return v;
}

__device__ __forceinline__ uint32_t f2tf(float x) {
    uint32_t r;
    asm("cvt.rna.tf32.f32 %0, %1;" : "=r"(r) : "f"(x));
    return r;
}

__device__ __forceinline__ void mma_tf32(float* d, const uint32_t* a, const uint32_t* b) {
    asm volatile(
        "mma.sync.aligned.m16n8k8.row.col.f32.tf32.tf32.f32 "
        "{%0,%1,%2,%3},{%4,%5,%6,%7},{%8,%9},{%0,%1,%2,%3};"
        : "+f"(d[0]), "+f"(d[1]), "+f"(d[2]), "+f"(d[3])
        : "r"(a[0]), "r"(a[1]), "r"(a[2]), "r"(a[3]), "r"(b[0]), "r"(b[1]));
}

// scatter-only prep: inverse map (idempotent atomicMax on zero-init arrays).
__global__ void k_scatter(const int* __restrict__ act, const int* __restrict__ nb) {
    int t = blockIdx.x * blockDim.x + threadIdx.x;
    if (t < SS) {
        int v = (t < NACT) ? act[t] : nb[t - NACT];
        atomicMax(&g_loE[v], SS - t);
        atomicMax(&g_hiE[v], t + 1);
    }
}

// ---------------------------------------------------------------------------
// fused main kernel (R10 known-good):
//   bid % 9 == 0 && bid < 2376 -> tf32 MMA GEMM tile (264): g_XW1 = x[cur] @ W1
//   bid < 2376 otherwise       -> extract block (2112): sparse row of adj[cur][:,cur]
//   bid >= 2376                -> g_w reduction block (128): g_w = W2 @ imp_w
// ---------------------------------------------------------------------------
#define AS_STRIDE 36
#define BS_STRIDE 72
#define SMEM_BYTES (64 * AS_STRIDE * 4 + 32 * BS_STRIDE * 4)

__global__ void __launch_bounds__(256) k_main(const float* __restrict__ X,
                                              const float* __restrict__ W1,
                                              const float* __restrict__ adj,
                                              const int* __restrict__ act,
                                              const int* __restrict__ nb,
                                              const float* __restrict__ W2,
                                              const float* __restrict__ iw) {
    __shared__ __align__(16) char smem_raw[SMEM_BYTES];
    __shared__ float s_gw[8];
    int bid = blockIdx.x;
    int tid = threadIdx.x;

    if (bid >= EXTRACT_END) {
        // ================= g_w reduction: 4 rows/block, 64 threads/row =========
        int widx = bid - EXTRACT_END;            // 0..127
        int row = widx * 4 + (tid >> 6);         // 0..511
        int t64 = tid & 63;
        int warp = tid >> 5, lane = tid & 31;
        float4 wv = *(const float4*)(W2 + (size_t)row * NOUT + t64 * 4);
        float4 iv = *(const float4*)(iw + t64 * 4);
        float p = wv.x * iv.x + wv.y * iv.y + wv.z * iv.z + wv.w * iv.w;
        p = warp_sum(p);                         // whole warp belongs to one row
        if (lane == 0) s_gw[warp] = p;
        __syncthreads();
        if (t64 == 0) g_w[row] = s_gw[(tid >> 6) * 2] + s_gw[(tid >> 6) * 2 + 1];
        return;
    }

    if (bid % 9 == 0) {
        // ================= tf32 MMA GEMM path =================
        int gidx = bid / 9;
        int bm = (gidx >> 3) * 64;
        int bn = (gidx & 7) * 64;
        uint32_t* As = (uint32_t*)smem_raw;
        uint32_t* Bs = As + 64 * AS_STRIDE;
        int warp = tid >> 5, lane = tid & 31;
        int wr = warp >> 2;
        int wc = warp & 3;

        float acc[2][2][4] = {};

        for (int k0 = 0; k0 < NFEAT; k0 += 32) {
            #pragma unroll
            for (int r = 0; r < 2; r++) {
                int f = tid + r * 256;
                int m = f >> 3, c4 = f & 7;
                int k = k0 + c4 * 4;
                float4 v = make_float4(0.f, 0.f, 0.f, 0.f);
                if (k < NFEAT) {
                    int gr = bm + m;
                    int node = (gr < NACT) ? act[gr] : nb[gr - NACT];
                    v = *(const float4*)(X + (size_t)node * NFEAT + k);
                }
                uint4 u = make_uint4(f2tf(v.x), f2tf(v.y), f2tf(v.z), f2tf(v.w));
                *(uint4*)&As[m * AS_STRIDE + c4 * 4] = u;
            }
            #pragma unroll
            for (int r = 0; r < 2; r++) {
                int f = tid + r * 256;
                int kr = f >> 4, c4 = f & 15;
                int k = k0 + kr;
                float4 v = make_float4(0.f, 0.f, 0.f, 0.f);
                if (k < NFEAT) v = *(const float4*)(W1 + (size_t)k * NHID + bn + c4 * 4);
                uint4 u = make_uint4(f2tf(v.x), f2tf(v.y), f2tf(v.z), f2tf(v.w));
                *(uint4*)&Bs[kr * BS_STRIDE + c4 * 4] = u;
            }
            __syncthreads();
            #pragma unroll
            for (int kk = 0; kk < 32; kk += 8) {
                uint32_t a[2][4], b[2][2];
                #pragma unroll
                for (int ti = 0; ti < 2; ti++) {
                    int r0 = wr * 32 + ti * 16 + (lane >> 2);
                    int kc = kk + (lane & 3);
                    a[ti][0] = As[r0 * AS_STRIDE + kc];
                    a[ti][1] = As[(r0 + 8) * AS_STRIDE + kc];
                    a[ti][2] = As[r0 * AS_STRIDE + kc + 4];
                    a[ti][3] = As[(r0 + 8) * AS_STRIDE + kc + 4];
                }
                #pragma unroll
                for (int tj = 0; tj < 2; tj++) {
                    int col = wc * 16 + tj * 8 + (lane >> 2);
                    int kc = kk + (lane & 3);
                    b[tj][0] = Bs[kc * BS_STRIDE + col];
                    b[tj][1] = Bs[(kc + 4) * BS_STRIDE + col];
                }
                #pragma unroll
                for (int ti = 0; ti < 2; ti++)
                    #pragma unroll
                    for (int tj = 0; tj < 2; tj++)
                        mma_tf32(acc[ti][tj], a[ti], b[tj]);
            }
            __syncthreads();
        }
        int lane4 = (tid & 31) >> 2, lm = (tid & 3) * 2;
        #pragma unroll
        for (int ti = 0; ti < 2; ti++) {
            int row0 = bm + wr * 32 + ti * 16 + lane4;
            #pragma unroll
            for (int tj = 0; tj < 2; tj++) {
                int col0 = bn + wc * 16 + tj * 8 + lm;
                float* c = acc[ti][tj];
                *(float2*)&g_XW1[(size_t)row0 * NHID + col0]       = make_float2(c[0], c[1]);
                *(float2*)&g_XW1[(size_t)(row0 + 8) * NHID + col0] = make_float2(c[2], c[3]);
            }
        }
    } else {
        // ================= extract path: stream one adjacency row =================
        int i = bid - bid / 9 - 1;
        int* s_cols   = (int*)smem_raw;
        int* s_sorted = s_cols + MAXNNZ;
        int* s_cntp   = s_sorted + MAXNNZ;
        if (tid == 0) *s_cntp = 0;
        __syncthreads();
        int node = (i < NACT) ? act[i] : nb[i - NACT];
        const float4* row = (const float4*)(adj + (size_t)node * NNODES);
        #pragma unroll 4
        for (int it = 0; it < NNODES / 4 / 256; it++) {
            int p = it * 256 + tid;
            float4 v = __ldcs(row + p);
            if (v.x != 0.f || v.y != 0.f || v.z != 0.f || v.w != 0.f) {
                float e[4] = {v.x, v.y, v.z, v.w};
                #pragma unroll
                for (int q = 0; q < 4; q++) {
                    if (e[q] != 0.f) {
                        int col = p * 4 + q;
                        int lov = g_loE[col];
                        if (lov > 0) {
                            int lo = SS - lov;
                            int k = atomicAdd(s_cntp, 1);
                            if (k < MAXNNZ) s_cols[k] = lo;
                            int hi = g_hiE[col] - 1;
                            if (hi != lo) {
                                k = atomicAdd(s_cntp, 1);
                                if (k < MAXNNZ) s_cols[k] = hi;
                            }
                        }
                    }
                }
            }
        }
        __syncthreads();
        int n = min(*s_cntp, MAXNNZ);
        if (tid < n) {
            int val = s_cols[tid];
            int rank = 0;
            for (int k = 0; k < n; k++) rank += (s_cols[k] < val);
            s_sorted[rank] = val;
        }
        __syncthreads();
        if (tid == 0) g_nnz[i] = n;
        if (tid < n) g_cols[i * MAXNNZ + tid] = s_sorted[tid];
    }
}

// layer2, float4 version: 2 rows per block (grid 1056), 128 threads per row.
// u[i] = relu(sum over sparse row of XW1) . w ; per-element k-order ascending
// (identical column summation order as before; 4x fewer L2 requests).
__global__ void __launch_bounds__(256) k_layer2() {
    __shared__ float s_w[NHID];
    __shared__ float s_red[2][4];
    int tid = threadIdx.x;
    int half = tid >> 7;                 // 0/1: row within the pair
    int lane128 = tid & 127;             // float4 slot within the 512-float row
    int warp = tid >> 5, lane = tid & 31;
    int i = blockIdx.x * 2 + half;

    s_w[tid] = g_w[tid];
    s_w[tid + 256] = g_w[tid + 256];
    __syncthreads();
    float4 w4 = *(const float4*)&s_w[lane128 * 4];

    int nnz = g_nnz[i];
    const int* cp = g_cols + i * MAXNNZ;
    float4 acc = make_float4(0.f, 0.f, 0.f, 0.f);
    for (int k0 = 0; k0 < nnz; k0 += 4) {
        float4 v[4];
        #pragma unroll
        for (int q = 0; q < 4; q++) {
            v[q] = make_float4(0.f, 0.f, 0.f, 0.f);
            if (k0 + q < nnz) {
                const float4* src = (const float4*)(g_XW1 + (size_t)cp[k0 + q] * NHID);
                v[q] = src[lane128];
            }
        }
        #pragma unroll
        for (int q = 0; q < 4; q++) {
            acc.x += v[q].x; acc.y += v[q].y; acc.z += v[q].z; acc.w += v[q].w;
        }
    }
    float p = fmaxf(acc.x, 0.f) * w4.x + fmaxf(acc.y, 0.f) * w4.y
            + fmaxf(acc.z, 0.f) * w4.z + fmaxf(acc.w, 0.f) * w4.w;
    p = warp_sum(p);
    if (lane == 0) s_red[half][warp & 3] = p;
    __syncthreads();
    if (lane128 == 0)
        g_u[i] = s_red[half][0] + s_red[half][1] + s_red[half][2] + s_red[half][3];
}

// finalize (known-good, 1024 threads): v = A@u; imp = A@v + b; L1-normalize.
__global__ void k_finalize(const float* __restrict__ impb, const int* __restrict__ nb,
                           float* __restrict__ out, int out_size) {
    __shared__ float s_u[SS];
    __shared__ float s_v[SS];
    __shared__ float s_imp[SS];
    __shared__ float s_red[32];
    __shared__ float s_tot;
    int tid = threadIdx.x;

    for (int j = tid; j < SS; j += 1024) s_u[j] = g_u[j];
    __syncthreads();

    for (int i = tid; i < SS; i += 1024) {
        int nnz = g_nnz[i];
        const int4* cp4 = (const int4*)(g_cols + i * MAXNNZ);
        float a = 0.f;
        for (int k0 = 0; k0 < nnz; k0 += 4) {
            int4 c = cp4[k0 >> 2];
            if (k0 + 0 < nnz) a += s_u[c.x];
            if (k0 + 1 < nnz) a += s_u[c.y];
            if (k0 + 2 < nnz) a += s_u[c.z];
            if (k0 + 3 < nnz) a += s_u[c.w];
        }
        s_v[i] = a;
    }
    __syncthreads();

    float b = impb[0];
    float part = 0.f;
    for (int i = tid; i < SS; i += 1024) {
        int nnz = g_nnz[i];
        const int4* cp4 = (const int4*)(g_cols + i * MAXNNZ);
        float a = b;
        for (int k0 = 0; k0 < nnz; k0 += 4) {
            int4 c = cp4[k0 >> 2];
            if (k0 + 0 < nnz) a += s_v[c.x];
            if (k0 + 1 < nnz) a += s_v[c.y];
            if (k0 + 2 < nnz) a += s_v[c.z];
            if (k0 + 3 < nnz) a += s_v[c.w];
        }
        s_imp[i] = a;
        part += fabsf(a);
    }
    part = warp_sum(part);
    if ((tid & 31) == 0) s_red[tid >> 5] = part;
    __syncthreads();
    if (tid == 0) {
        float s = 0.f;
        #pragma unroll
        for (int w = 0; w < 32; w++) s += s_red[w];
        s_tot = s;
    }
    __syncthreads();
    float inv = 1.f / fmaxf(s_tot, 1e-12f);
    for (int j = tid; j < NEIGH; j += 1024) out[j] = s_imp[NACT + j] * inv;
    if (out_size >= 2 * NEIGH)
        for (int j = tid; j < NEIGH; j += 1024) out[NEIGH + j] = (float)nb[j];
}

extern "C" void kernel_launch(void* const* d_in, const int* in_sizes, int n_in,
                              void* d_out, int out_size) {
    const float* x   = (const float*)d_in[0];
    const float* adj = (const float*)d_in[1];
    const int*   act = (const int*)d_in[2];
    const int*   nb  = (const int*)d_in[3];
    const float* W1  = (const float*)d_in[4];
    const float* W2  = (const float*)d_in[5];
    const float* iw  = (const float*)d_in[6];
    const float* ib  = (const float*)d_in[7];
    float* out = (float*)d_out;
    (void)in_sizes; (void)n_in;

    k_scatter<<<(SS + 255) / 256, 256>>>(act, nb);
    k_main<<<MAIN_BLOCKS, 256>>>(x, W1, adj, act, nb, W2, iw);
    k_layer2<<<SS / 2, 256>>>();
    k_finalize<<<1, 1024>>>(ib, nb, out, out_size);
}

// round 16
// speedup vs baseline: 1.1709x; 1.0562x over previous
#include <cuda_runtime.h>
#include <cstdint>

#define NNODES 16384
#define NFEAT  300
#define NHID   512
#define NOUT   256
#define NACT   64
#define NEIGH  2048
#define SS     2112      // NACT + NEIGH
#define MAXNNZ 64

#define GEMM_BLOCKS 264                       // 33 row-tiles x 8 col-tiles of 64
#define EXTRACT_END (GEMM_BLOCKS + SS)        // 2376 = 264 * 9
#define W_BLOCKS    128                       // g_w reduction: 4 rows/block
#define MAIN_BLOCKS (EXTRACT_END + W_BLOCKS)  // 2504
#define FIN_BLOCKS  ((SS + 255) / 256)        // 9

// ---- scratch (static device globals; zero-initialized at module load) ----
__device__ int   g_loE[NNODES];    // atomicMax of (SS - j); 0 = absent; lo = SS - val
__device__ int   g_hiE[NNODES];    // atomicMax of (j + 1);  0 = absent; hi = val - 1
__device__ int   g_nnz[SS];
__device__ int   g_cols[SS * MAXNNZ];
__device__ float g_XW1[SS * NHID]; // x[cur] @ W1
__device__ float g_w[NHID];        // W2 @ imp_w
__device__ float g_u[SS];          // relu(A @ XW1) @ w
__device__ float g_v[SS];          // A @ u
__device__ float g_imp[SS];        // A @ v + b
__device__ float g_part[FIN_BLOCKS]; // per-block L1 partials (overwritten each replay)

__device__ __forceinline__ float warp_sum(float v) {
    #pragma unroll
    for (int o = 16; o > 0; o >>= 1) v += __shfl_xor_sync(0xFFFFFFFFu, v, o);
    return v;
}

__device__ __forceinline__ uint32_t f2tf(float x) {
    uint32_t r;
    asm("cvt.rna.tf32.f32 %0, %1;" : "=r"(r) : "f"(x));
    return r;
}

__device__ __forceinline__ void mma_tf32(float* d, const uint32_t* a, const uint32_t* b) {
    asm volatile(
        "mma.sync.aligned.m16n8k8.row.col.f32.tf32.tf32.f32 "
        "{%0,%1,%2,%3},{%4,%5,%6,%7},{%8,%9},{%0,%1,%2,%3};"
        : "+f"(d[0]), "+f"(d[1]), "+f"(d[2]), "+f"(d[3])
        : "r"(a[0]), "r"(a[1]), "r"(a[2]), "r"(a[3]), "r"(b[0]), "r"(b[1]));
}

// scatter-only prep: inverse map (idempotent atomicMax on zero-init arrays).
__global__ void k_scatter(const int* __restrict__ act, const int* __restrict__ nb) {
    int t = blockIdx.x * blockDim.x + threadIdx.x;
    if (t < SS) {
        int v = (t < NACT) ? act[t] : nb[t - NACT];
        atomicMax(&g_loE[v], SS - t);
        atomicMax(&g_hiE[v], t + 1);
    }
}

// ---------------------------------------------------------------------------
// fused main kernel (R10 known-good):
//   bid % 9 == 0 && bid < 2376 -> tf32 MMA GEMM tile (264): g_XW1 = x[cur] @ W1
//   bid < 2376 otherwise       -> extract block (2112): sparse row of adj[cur][:,cur]
//   bid >= 2376                -> g_w reduction block (128): g_w = W2 @ imp_w
// ---------------------------------------------------------------------------
#define AS_STRIDE 36
#define BS_STRIDE 72
#define SMEM_BYTES (64 * AS_STRIDE * 4 + 32 * BS_STRIDE * 4)

__global__ void __launch_bounds__(256) k_main(const float* __restrict__ X,
                                              const float* __restrict__ W1,
                                              const float* __restrict__ adj,
                                              const int* __restrict__ act,
                                              const int* __restrict__ nb,
                                              const float* __restrict__ W2,
                                              const float* __restrict__ iw) {
    __shared__ __align__(16) char smem_raw[SMEM_BYTES];
    __shared__ float s_gw[8];
    int bid = blockIdx.x;
    int tid = threadIdx.x;

    if (bid >= EXTRACT_END) {
        // ================= g_w reduction: 4 rows/block, 64 threads/row =========
        int widx = bid - EXTRACT_END;            // 0..127
        int row = widx * 4 + (tid >> 6);         // 0..511
        int t64 = tid & 63;
        int warp = tid >> 5, lane = tid & 31;
        float4 wv = *(const float4*)(W2 + (size_t)row * NOUT + t64 * 4);
        float4 iv = *(const float4*)(iw + t64 * 4);
        float p = wv.x * iv.x + wv.y * iv.y + wv.z * iv.z + wv.w * iv.w;
        p = warp_sum(p);                         // whole warp belongs to one row
        if (lane == 0) s_gw[warp] = p;
        __syncthreads();
        if (t64 == 0) g_w[row] = s_gw[(tid >> 6) * 2] + s_gw[(tid >> 6) * 2 + 1];
        return;
    }

    if (bid % 9 == 0) {
        // ================= tf32 MMA GEMM path =================
        int gidx = bid / 9;
        int bm = (gidx >> 3) * 64;
        int bn = (gidx & 7) * 64;
        uint32_t* As = (uint32_t*)smem_raw;
        uint32_t* Bs = As + 64 * AS_STRIDE;
        int warp = tid >> 5, lane = tid & 31;
        int wr = warp >> 2;
        int wc = warp & 3;

        float acc[2][2][4] = {};

        for (int k0 = 0; k0 < NFEAT; k0 += 32) {
            #pragma unroll
            for (int r = 0; r < 2; r++) {
                int f = tid + r * 256;
                int m = f >> 3, c4 = f & 7;
                int k = k0 + c4 * 4;
                float4 v = make_float4(0.f, 0.f, 0.f, 0.f);
                if (k < NFEAT) {
                    int gr = bm + m;
                    int node = (gr < NACT) ? act[gr] : nb[gr - NACT];
                    v = *(const float4*)(X + (size_t)node * NFEAT + k);
                }
                uint4 u = make_uint4(f2tf(v.x), f2tf(v.y), f2tf(v.z), f2tf(v.w));
                *(uint4*)&As[m * AS_STRIDE + c4 * 4] = u;
            }
            #pragma unroll
            for (int r = 0; r < 2; r++) {
                int f = tid + r * 256;
                int kr = f >> 4, c4 = f & 15;
                int k = k0 + kr;
                float4 v = make_float4(0.f, 0.f, 0.f, 0.f);
                if (k < NFEAT) v = *(const float4*)(W1 + (size_t)k * NHID + bn + c4 * 4);
                uint4 u = make_uint4(f2tf(v.x), f2tf(v.y), f2tf(v.z), f2tf(v.w));
                *(uint4*)&Bs[kr * BS_STRIDE + c4 * 4] = u;
            }
            __syncthreads();
            #pragma unroll
            for (int kk = 0; kk < 32; kk += 8) {
                uint32_t a[2][4], b[2][2];
                #pragma unroll
                for (int ti = 0; ti < 2; ti++) {
                    int r0 = wr * 32 + ti * 16 + (lane >> 2);
                    int kc = kk + (lane & 3);
                    a[ti][0] = As[r0 * AS_STRIDE + kc];
                    a[ti][1] = As[(r0 + 8) * AS_STRIDE + kc];
                    a[ti][2] = As[r0 * AS_STRIDE + kc + 4];
                    a[ti][3] = As[(r0 + 8) * AS_STRIDE + kc + 4];
                }
                #pragma unroll
                for (int tj = 0; tj < 2; tj++) {
                    int col = wc * 16 + tj * 8 + (lane >> 2);
                    int kc = kk + (lane & 3);
                    b[tj][0] = Bs[kc * BS_STRIDE + col];
                    b[tj][1] = Bs[(kc + 4) * BS_STRIDE + col];
                }
                #pragma unroll
                for (int ti = 0; ti < 2; ti++)
                    #pragma unroll
                    for (int tj = 0; tj < 2; tj++)
                        mma_tf32(acc[ti][tj], a[ti], b[tj]);
            }
            __syncthreads();
        }
        int lane4 = (tid & 31) >> 2, lm = (tid & 3) * 2;
        #pragma unroll
        for (int ti = 0; ti < 2; ti++) {
            int row0 = bm + wr * 32 + ti * 16 + lane4;
            #pragma unroll
            for (int tj = 0; tj < 2; tj++) {
                int col0 = bn + wc * 16 + tj * 8 + lm;
                float* c = acc[ti][tj];
                *(float2*)&g_XW1[(size_t)row0 * NHID + col0]       = make_float2(c[0], c[1]);
                *(float2*)&g_XW1[(size_t)(row0 + 8) * NHID + col0] = make_float2(c[2], c[3]);
            }
        }
    } else {
        // ================= extract path: stream one adjacency row =================
        int i = bid - bid / 9 - 1;
        int* s_cols   = (int*)smem_raw;
        int* s_sorted = s_cols + MAXNNZ;
        int* s_cntp   = s_sorted + MAXNNZ;
        if (tid == 0) *s_cntp = 0;
        __syncthreads();
        int node = (i < NACT) ? act[i] : nb[i - NACT];
        const float4* row = (const float4*)(adj + (size_t)node * NNODES);
        #pragma unroll 4
        for (int it = 0; it < NNODES / 4 / 256; it++) {
            int p = it * 256 + tid;
            float4 v = __ldcs(row + p);
            if (v.x != 0.f || v.y != 0.f || v.z != 0.f || v.w != 0.f) {
                float e[4] = {v.x, v.y, v.z, v.w};
                #pragma unroll
                for (int q = 0; q < 4; q++) {
                    if (e[q] != 0.f) {
                        int col = p * 4 + q;
                        int lov = g_loE[col];
                        if (lov > 0) {
                            int lo = SS - lov;
                            int k = atomicAdd(s_cntp, 1);
                            if (k < MAXNNZ) s_cols[k] = lo;
                            int hi = g_hiE[col] - 1;
                            if (hi != lo) {
                                k = atomicAdd(s_cntp, 1);
                                if (k < MAXNNZ) s_cols[k] = hi;
                            }
                        }
                    }
                }
            }
        }
        __syncthreads();
        int n = min(*s_cntp, MAXNNZ);
        if (tid < n) {
            int val = s_cols[tid];
            int rank = 0;
            for (int k = 0; k < n; k++) rank += (s_cols[k] < val);
            s_sorted[rank] = val;
        }
        __syncthreads();
        if (tid == 0) g_nnz[i] = n;
        if (tid < n) g_cols[i * MAXNNZ + tid] = s_sorted[tid];
    }
}

// layer2 (R10 known-good scalar): u[i] = relu(sum over sparse row of XW1) . w
__global__ void k_layer2() {
    __shared__ float s_w[NHID];
    __shared__ float s_red[8];
    int i = blockIdx.x, tid = threadIdx.x;
    s_w[tid] = g_w[tid];
    s_w[tid + 256] = g_w[tid + 256];
    __syncthreads();
    int nnz = g_nnz[i];
    const int* cp = g_cols + i * MAXNNZ;
    float a0 = 0.f, a1 = 0.f;
    for (int k0 = 0; k0 < nnz; k0 += 8) {
        float v0[8], v1[8];
        #pragma unroll
        for (int q = 0; q < 8; q++) {
            float x0 = 0.f, x1 = 0.f;
            int kk = k0 + q;
            if (kk < nnz) {
                const float* s = g_XW1 + (size_t)cp[kk] * NHID;
                x0 = s[tid];
                x1 = s[tid + 256];
            }
            v0[q] = x0; v1[q] = x1;
        }
        #pragma unroll
        for (int q = 0; q < 8; q++) { a0 += v0[q]; a1 += v1[q]; }
    }
    float p = fmaxf(a0, 0.f) * s_w[tid] + fmaxf(a1, 0.f) * s_w[tid + 256];
    p = warp_sum(p);
    if ((tid & 31) == 0) s_red[tid >> 5] = p;
    __syncthreads();
    if (tid == 0) {
        float s = 0.f;
        #pragma unroll
        for (int w = 0; w < 8; w++) s += s_red[w];
        g_u[i] = s;
    }
}

// v = A @ u, thread-per-row across the chip (ascending-k order preserved).
__global__ void __launch_bounds__(256) k_vpass() {
    int i = blockIdx.x * 256 + threadIdx.x;
    if (i >= SS) return;
    int nnz = g_nnz[i];
    const int4* cp4 = (const int4*)(g_cols + i * MAXNNZ);
    float a = 0.f;
    for (int k0 = 0; k0 < nnz; k0 += 4) {
        int4 c = cp4[k0 >> 2];
        if (k0 + 0 < nnz) a += g_u[c.x];
        if (k0 + 1 < nnz) a += g_u[c.y];
        if (k0 + 2 < nnz) a += g_u[c.z];
        if (k0 + 3 < nnz) a += g_u[c.w];
    }
    g_v[i] = a;
}

// imp = A @ v + b; per-block L1 partial via fixed warp/block tree (deterministic).
__global__ void __launch_bounds__(256) k_ipass(const float* __restrict__ impb) {
    __shared__ float s_red[8];
    int tid = threadIdx.x;
    int warp = tid >> 5, lane = tid & 31;
    int i = blockIdx.x * 256 + tid;
    float aa = 0.f;
    if (i < SS) {
        int nnz = g_nnz[i];
        const int4* cp4 = (const int4*)(g_cols + i * MAXNNZ);
        float a = impb[0];
        for (int k0 = 0; k0 < nnz; k0 += 4) {
            int4 c = cp4[k0 >> 2];
            if (k0 + 0 < nnz) a += g_v[c.x];
            if (k0 + 1 < nnz) a += g_v[c.y];
            if (k0 + 2 < nnz) a += g_v[c.z];
            if (k0 + 3 < nnz) a += g_v[c.w];
        }
        g_imp[i] = a;
        aa = fabsf(a);
    }
    float p = warp_sum(aa);
    if (lane == 0) s_red[warp] = p;
    __syncthreads();
    if (tid == 0) {
        float s = 0.f;
        #pragma unroll
        for (int w = 0; w < 8; w++) s += s_red[w];
        g_part[blockIdx.x] = s;
    }
}

// norm + output: sum 9 partials in fixed order, scale, write.
__global__ void k_norm(const int* __restrict__ nb, float* __restrict__ out, int out_size) {
    __shared__ float s_tot;
    int tid = threadIdx.x;
    if (tid == 0) {
        float s = 0.f;
        #pragma unroll
        for (int w = 0; w < FIN_BLOCKS; w++) s += g_part[w];
        s_tot = s;
    }
    __syncthreads();
    float inv = 1.f / fmaxf(s_tot, 1e-12f);
    for (int j = tid; j < NEIGH; j += 1024) out[j] = g_imp[NACT + j] * inv;
    if (out_size >= 2 * NEIGH)
        for (int j = tid; j < NEIGH; j += 1024) out[NEIGH + j] = (float)nb[j];
}

extern "C" void kernel_launch(void* const* d_in, const int* in_sizes, int n_in,
                              void* d_out, int out_size) {
    const float* x   = (const float*)d_in[0];
    const float* adj = (const float*)d_in[1];
    const int*   act = (const int*)d_in[2];
    const int*   nb  = (const int*)d_in[3];
    const float* W1  = (const float*)d_in[4];
    const float* W2  = (const float*)d_in[5];
    const float* iw  = (const float*)d_in[6];
    const float* ib  = (const float*)d_in[7];
    float* out = (float*)d_out;
    (void)in_sizes; (void)n_in;

    k_scatter<<<(SS + 255) / 256, 256>>>(act, nb);
    k_main<<<MAIN_BLOCKS, 256>>>(x, W1, adj, act, nb, W2, iw);
    k_layer2<<<SS, 256>>>();
    k_vpass<<<FIN_BLOCKS, 256>>>();
    k_ipass<<<FIN_BLOCKS, 256>>>(ib);
    k_norm<<<1, 1024>>>(nb, out, out_size);
}

// round 17
// speedup vs baseline: 1.3638x; 1.1648x over previous
#include <cuda_runtime.h>
#include <cstdint>

#define NNODES 16384
#define NFEAT  300
#define NHID   512
#define NOUT   256
#define NACT   64
#define NEIGH  2048
#define SS     2112      // NACT + NEIGH
#define MAXNNZ 64

#define GEMM_BLOCKS 264                       // 33 row-tiles x 8 col-tiles of 64
#define EXTRACT_END (GEMM_BLOCKS + SS)        // 2376 = 264 * 9
#define W_BLOCKS    128                       // g_w reduction: 4 rows/block
#define MAIN_BLOCKS (EXTRACT_END + W_BLOCKS)  // 2504
#define FIN_BLOCKS  ((SS + 255) / 256)        // 9

// ---- scratch (static device globals; zero-initialized at module load) ----
__device__ int   g_loE[NNODES];    // atomicMax of (SS - j); 0 = absent; lo = SS - val
__device__ int   g_hiE[NNODES];    // atomicMax of (j + 1);  0 = absent; hi = val - 1
__device__ int   g_nnz[SS];
__device__ int   g_cols[SS * MAXNNZ];
__device__ float g_XW1[SS * NHID]; // x[cur] @ W1
__device__ float g_w[NHID];        // W2 @ imp_w
__device__ float g_u[SS];          // relu(A @ XW1) @ w
__device__ float g_v[SS];          // A @ u
__device__ float g_imp[SS];        // A @ v + b
__device__ float g_part[FIN_BLOCKS]; // per-block L1 partials (overwritten each replay)

__device__ __forceinline__ float warp_sum(float v) {
    #pragma unroll
    for (int o = 16; o > 0; o >>= 1) v += __shfl_xor_sync(0xFFFFFFFFu, v, o);
    return v;
}

__device__ __forceinline__ uint32_t f2tf(float x) {
    uint32_t r;
    asm("cvt.rna.tf32.f32 %0, %1;" : "=r"(r) : "f"(x));
    return r;
}

__device__ __forceinline__ void mma_tf32(float* d, const uint32_t* a, const uint32_t* b) {
    asm volatile(
        "mma.sync.aligned.m16n8k8.row.col.f32.tf32.tf32.f32 "
        "{%0,%1,%2,%3},{%4,%5,%6,%7},{%8,%9},{%0,%1,%2,%3};"
        : "+f"(d[0]), "+f"(d[1]), "+f"(d[2]), "+f"(d[3])
        : "r"(a[0]), "r"(a[1]), "r"(a[2]), "r"(a[3]), "r"(b[0]), "r"(b[1]));
}

// scatter-only prep: inverse map (idempotent atomicMax on zero-init arrays).
__global__ void k_scatter(const int* __restrict__ act, const int* __restrict__ nb) {
    int t = blockIdx.x * blockDim.x + threadIdx.x;
    if (t < SS) {
        int v = (t < NACT) ? act[t] : nb[t - NACT];
        atomicMax(&g_loE[v], SS - t);
        atomicMax(&g_hiE[v], t + 1);
    }
}

// ---------------------------------------------------------------------------
// fused main kernel:
//   bid % 9 == 0 && bid < 2376 -> tf32 MMA GEMM tile (264): g_XW1 = x[cur] @ W1
//   bid < 2376 otherwise       -> extract block (2112): sparse row of adj[cur][:,cur]
//   bid >= 2376                -> g_w reduction block (128): g_w = W2 @ imp_w
// ---------------------------------------------------------------------------
#define AS_STRIDE 36
#define BS_STRIDE 72
#define SMEM_BYTES (64 * AS_STRIDE * 4 + 32 * BS_STRIDE * 4)

__global__ void __launch_bounds__(256) k_main(const float* __restrict__ X,
                                              const float* __restrict__ W1,
                                              const float* __restrict__ adj,
                                              const int* __restrict__ act,
                                              const int* __restrict__ nb,
                                              const float* __restrict__ W2,
                                              const float* __restrict__ iw) {
    __shared__ __align__(16) char smem_raw[SMEM_BYTES];
    __shared__ float s_gw[8];
    int bid = blockIdx.x;
    int tid = threadIdx.x;

    if (bid >= EXTRACT_END) {
        // ================= g_w reduction: 4 rows/block, 64 threads/row =========
        int widx = bid - EXTRACT_END;            // 0..127
        int row = widx * 4 + (tid >> 6);         // 0..511
        int t64 = tid & 63;
        int warp = tid >> 5, lane = tid & 31;
        float4 wv = *(const float4*)(W2 + (size_t)row * NOUT + t64 * 4);
        float4 iv = *(const float4*)(iw + t64 * 4);
        float p = wv.x * iv.x + wv.y * iv.y + wv.z * iv.z + wv.w * iv.w;
        p = warp_sum(p);                         // whole warp belongs to one row
        if (lane == 0) s_gw[warp] = p;
        __syncthreads();
        if (t64 == 0) g_w[row] = s_gw[(tid >> 6) * 2] + s_gw[(tid >> 6) * 2 + 1];
        return;
    }

    if (bid % 9 == 0) {
        // ================= tf32 MMA GEMM path =================
        int gidx = bid / 9;
        int bm = (gidx >> 3) * 64;
        int bn = (gidx & 7) * 64;
        uint32_t* As = (uint32_t*)smem_raw;
        uint32_t* Bs = As + 64 * AS_STRIDE;
        int warp = tid >> 5, lane = tid & 31;
        int wr = warp >> 2;
        int wc = warp & 3;

        float acc[2][2][4] = {};

        for (int k0 = 0; k0 < NFEAT; k0 += 32) {
            #pragma unroll
            for (int r = 0; r < 2; r++) {
                int f = tid + r * 256;
                int m = f >> 3, c4 = f & 7;
                int k = k0 + c4 * 4;
                float4 v = make_float4(0.f, 0.f, 0.f, 0.f);
                if (k < NFEAT) {
                    int gr = bm + m;
                    int node = (gr < NACT) ? act[gr] : nb[gr - NACT];
                    v = *(const float4*)(X + (size_t)node * NFEAT + k);
                }
                uint4 u = make_uint4(f2tf(v.x), f2tf(v.y), f2tf(v.z), f2tf(v.w));
                *(uint4*)&As[m * AS_STRIDE + c4 * 4] = u;
            }
            #pragma unroll
            for (int r = 0; r < 2; r++) {
                int f = tid + r * 256;
                int kr = f >> 4, c4 = f & 15;
                int k = k0 + kr;
                float4 v = make_float4(0.f, 0.f, 0.f, 0.f);
                if (k < NFEAT) v = *(const float4*)(W1 + (size_t)k * NHID + bn + c4 * 4);
                uint4 u = make_uint4(f2tf(v.x), f2tf(v.y), f2tf(v.z), f2tf(v.w));
                *(uint4*)&Bs[kr * BS_STRIDE + c4 * 4] = u;
            }
            __syncthreads();
            #pragma unroll
            for (int kk = 0; kk < 32; kk += 8) {
                uint32_t a[2][4], b[2][2];
                #pragma unroll
                for (int ti = 0; ti < 2; ti++) {
                    int r0 = wr * 32 + ti * 16 + (lane >> 2);
                    int kc = kk + (lane & 3);
                    a[ti][0] = As[r0 * AS_STRIDE + kc];
                    a[ti][1] = As[(r0 + 8) * AS_STRIDE + kc];
                    a[ti][2] = As[r0 * AS_STRIDE + kc + 4];
                    a[ti][3] = As[(r0 + 8) * AS_STRIDE + kc + 4];
                }
                #pragma unroll
                for (int tj = 0; tj < 2; tj++) {
                    int col = wc * 16 + tj * 8 + (lane >> 2);
                    int kc = kk + (lane & 3);
                    b[tj][0] = Bs[kc * BS_STRIDE + col];
                    b[tj][1] = Bs[(kc + 4) * BS_STRIDE + col];
                }
                #pragma unroll
                for (int ti = 0; ti < 2; ti++)
                    #pragma unroll
                    for (int tj = 0; tj < 2; tj++)
                        mma_tf32(acc[ti][tj], a[ti], b[tj]);
            }
            __syncthreads();
        }
        int lane4 = (tid & 31) >> 2, lm = (tid & 3) * 2;
        #pragma unroll
        for (int ti = 0; ti < 2; ti++) {
            int row0 = bm + wr * 32 + ti * 16 + lane4;
            #pragma unroll
            for (int tj = 0; tj < 2; tj++) {
                int col0 = bn + wc * 16 + tj * 8 + lm;
                float* c = acc[ti][tj];
                *(float2*)&g_XW1[(size_t)row0 * NHID + col0]       = make_float2(c[0], c[1]);
                *(float2*)&g_XW1[(size_t)(row0 + 8) * NHID + col0] = make_float2(c[2], c[3]);
            }
        }
    } else {
        // ===== extract path: stream one adjacency row, batch-prefetch depth 8 =====
        int i = bid - bid / 9 - 1;
        int* s_cols   = (int*)smem_raw;
        int* s_sorted = s_cols + MAXNNZ;
        int* s_cntp   = s_sorted + MAXNNZ;
        if (tid == 0) *s_cntp = 0;
        __syncthreads();
        int node = (i < NACT) ? act[i] : nb[i - NACT];
        const float4* row = (const float4*)(adj + (size_t)node * NNODES);
        // 4096 float4s per row; 256 threads; 16 strided passes = 2 outer x 8 batch
        for (int it = 0; it < 2; it++) {
            float4 v[8];
            #pragma unroll
            for (int q = 0; q < 8; q++)
                v[q] = __ldcs(row + it * 2048 + q * 256 + tid);   // 8 loads in flight
            #pragma unroll
            for (int q = 0; q < 8; q++) {
                float4 vv = v[q];
                if (vv.x != 0.f || vv.y != 0.f || vv.z != 0.f || vv.w != 0.f) {
                    int p = it * 2048 + q * 256 + tid;
                    float e[4] = {vv.x, vv.y, vv.z, vv.w};
                    #pragma unroll
                    for (int r = 0; r < 4; r++) {
                        if (e[r] != 0.f) {
                            int col = p * 4 + r;
                            int lov = g_loE[col];
                            if (lov > 0) {
                                int lo = SS - lov;
                                int k = atomicAdd(s_cntp, 1);
                                if (k < MAXNNZ) s_cols[k] = lo;
                                int hi = g_hiE[col] - 1;
                                if (hi != lo) {
                                    k = atomicAdd(s_cntp, 1);
                                    if (k < MAXNNZ) s_cols[k] = hi;
                                }
                            }
                        }
                    }
                }
            }
        }
        __syncthreads();
        int n = min(*s_cntp, MAXNNZ);
        if (tid < n) {                      // rank-sort (values distinct)
            int val = s_cols[tid];
            int rank = 0;
            for (int k = 0; k < n; k++) rank += (s_cols[k] < val);
            s_sorted[rank] = val;
        }
        __syncthreads();
        if (tid == 0) g_nnz[i] = n;
        if (tid < n) g_cols[i * MAXNNZ + tid] = s_sorted[tid];
    }
}

// layer2 (known-good scalar): u[i] = relu(sum over sparse row of XW1) . w
__global__ void k_layer2() {
    __shared__ float s_w[NHID];
    __shared__ float s_red[8];
    int i = blockIdx.x, tid = threadIdx.x;
    s_w[tid] = g_w[tid];
    s_w[tid + 256] = g_w[tid + 256];
    __syncthreads();
    int nnz = g_nnz[i];
    const int* cp = g_cols + i * MAXNNZ;
    float a0 = 0.f, a1 = 0.f;
    for (int k0 = 0; k0 < nnz; k0 += 8) {
        float v0[8], v1[8];
        #pragma unroll
        for (int q = 0; q < 8; q++) {
            float x0 = 0.f, x1 = 0.f;
            int kk = k0 + q;
            if (kk < nnz) {
                const float* s = g_XW1 + (size_t)cp[kk] * NHID;
                x0 = s[tid];
                x1 = s[tid + 256];
            }
            v0[q] = x0; v1[q] = x1;
        }
        #pragma unroll
        for (int q = 0; q < 8; q++) { a0 += v0[q]; a1 += v1[q]; }
    }
    float p = fmaxf(a0, 0.f) * s_w[tid] + fmaxf(a1, 0.f) * s_w[tid + 256];
    p = warp_sum(p);
    if ((tid & 31) == 0) s_red[tid >> 5] = p;
    __syncthreads();
    if (tid == 0) {
        float s = 0.f;
        #pragma unroll
        for (int w = 0; w < 8; w++) s += s_red[w];
        g_u[i] = s;
    }
}

// v = A @ u, thread-per-row across the chip (ascending-k order preserved).
__global__ void __launch_bounds__(256) k_vpass() {
    int i = blockIdx.x * 256 + threadIdx.x;
    if (i >= SS) return;
    int nnz = g_nnz[i];
    const int4* cp4 = (const int4*)(g_cols + i * MAXNNZ);
    float a = 0.f;
    for (int k0 = 0; k0 < nnz; k0 += 4) {
        int4 c = cp4[k0 >> 2];
        if (k0 + 0 < nnz) a += g_u[c.x];
        if (k0 + 1 < nnz) a += g_u[c.y];
        if (k0 + 2 < nnz) a += g_u[c.z];
        if (k0 + 3 < nnz) a += g_u[c.w];
    }
    g_v[i] = a;
}

// imp = A @ v + b; per-block L1 partial via fixed warp/block tree (deterministic).
__global__ void __launch_bounds__(256) k_ipass(const float* __restrict__ impb) {
    __shared__ float s_red[8];
    int tid = threadIdx.x;
    int warp = tid >> 5, lane = tid & 31;
    int i = blockIdx.x * 256 + tid;
    float aa = 0.f;
    if (i < SS) {
        int nnz = g_nnz[i];
        const int4* cp4 = (const int4*)(g_cols + i * MAXNNZ);
        float a = impb[0];
        for (int k0 = 0; k0 < nnz; k0 += 4) {
            int4 c = cp4[k0 >> 2];
            if (k0 + 0 < nnz) a += g_v[c.x];
            if (k0 + 1 < nnz) a += g_v[c.y];
            if (k0 + 2 < nnz) a += g_v[c.z];
            if (k0 + 3 < nnz) a += g_v[c.w];
        }
        g_imp[i] = a;
        aa = fabsf(a);
    }
    float p = warp_sum(aa);
    if (lane == 0) s_red[warp] = p;
    __syncthreads();
    if (tid == 0) {
        float s = 0.f;
        #pragma unroll
        for (int w = 0; w < 8; w++) s += s_red[w];
        g_part[blockIdx.x] = s;
    }
}

// norm + output: sum 9 partials in fixed order, scale, write.
__global__ void k_norm(const int* __restrict__ nb, float* __restrict__ out, int out_size) {
    __shared__ float s_tot;
    int tid = threadIdx.x;
    if (tid == 0) {
        float s = 0.f;
        #pragma unroll
        for (int w = 0; w < FIN_BLOCKS; w++) s += g_part[w];
        s_tot = s;
    }
    __syncthreads();
    float inv = 1.f / fmaxf(s_tot, 1e-12f);
    for (int j = tid; j < NEIGH; j += 1024) out[j] = g_imp[NACT + j] * inv;
    if (out_size >= 2 * NEIGH)
        for (int j = tid; j < NEIGH; j += 1024) out[NEIGH + j] = (float)nb[j];
}

extern "C" void kernel_launch(void* const* d_in, const int* in_sizes, int n_in,
                              void* d_out, int out_size) {
    const float* x   = (const float*)d_in[0];
    const float* adj = (const float*)d_in[1];
    const int*   act = (const int*)d_in[2];
    const int*   nb  = (const int*)d_in[3];
    const float* W1  = (const float*)d_in[4];
    const float* W2  = (const float*)d_in[5];
    const float* iw  = (const float*)d_in[6];
    const float* ib  = (const float*)d_in[7];
    float* out = (float*)d_out;
    (void)in_sizes; (void)n_in;

    k_scatter<<<(SS + 255) / 256, 256>>>(act, nb);
    k_main<<<MAIN_BLOCKS, 256>>>(x, W1, adj, act, nb, W2, iw);
    k_layer2<<<SS, 256>>>();
    k_vpass<<<FIN_BLOCKS, 256>>>();
    k_ipass<<<FIN_BLOCKS, 256>>>(ib);
    k_norm<<<1, 1024>>>(nb, out, out_size);
}